// round 15
// baseline (speedup 1.0000x reference)
#include <cuda_runtime.h>

#define BB   4
#define NN   8000
#define CC   64
#define KK   32
#define DD   9
#define NCLS 13
#define BN   (BB*NN)

#define CHUNK 2000        // candidates per smem chunk (32KB SoA), 4 chunks
#define CAPG  80          // group-entry append slots per thread (u32, smem)
// smem: 32000 (chunk SoA) + 65536 (32 u64 result slots) + 81920 (appends)

__device__ float  g_G1[BN*CC];
__device__ float  g_G2[BN*CC];
__device__ float4 g_pts[BN];
__device__ int    g_idx[BN*KK];
__device__ float  g_C1[CC*CC], g_C2[CC*CC], g_c1[CC], g_c2[CC];

__device__ __forceinline__ float inf_f() { return __int_as_float(0x7f800000); }

#define FMA2(d,a,b,c) asm("fma.rn.f32x2 %0, %1, %2, %3;" : "=l"(d) : "l"(a), "l"(b), "l"(c))
#define ADD2(d,a,b)   asm("add.rn.f32x2 %0, %1, %2;" : "=l"(d) : "l"(a), "l"(b))
#define PK2(d,lo,hi)  asm("mov.b64 %0, {%1, %2};" : "=l"(d) : "f"(lo), "f"(hi))
#define UPK2(lo,hi,d) asm("mov.b64 {%0, %1}, %2;" : "=f"(lo), "=f"(hi) : "l"(d))

// ---------------------------------------------------------------------------
// Precompute: C1 = w2@f1w, C2 = w2@f2w, c1 = b2@f1w, c2 = b2@f2w.
// ---------------------------------------------------------------------------
__global__ __launch_bounds__(256) void precompute_kernel(
    const float* __restrict__ w2, const float* __restrict__ b2v,
    const float* __restrict__ f1w, const float* __restrict__ f2w)
{
    int idx = blockIdx.x*256 + threadIdx.x;
    if (idx < CC*CC) {
        int r = idx / CC, c = idx % CC;
        float a = 0.f;
        #pragma unroll 4
        for (int k = 0; k < CC; k++) a = fmaf(w2[r*CC+k], f1w[k*CC+c], a);
        g_C1[idx] = a;
    } else if (idx < 2*CC*CC) {
        int t = idx - CC*CC;
        int r = t / CC, c = t % CC;
        float a = 0.f;
        #pragma unroll 4
        for (int k = 0; k < CC; k++) a = fmaf(w2[r*CC+k], f2w[k*CC+c], a);
        g_C2[t] = a;
    } else if (idx < 2*CC*CC + CC) {
        int c = idx - 2*CC*CC;
        float a = 0.f;
        #pragma unroll 4
        for (int k = 0; k < CC; k++) a = fmaf(b2v[k], f1w[k*CC+c], a);
        g_c1[c] = a;
    } else if (idx < 2*CC*CC + 2*CC) {
        int c = idx - 2*CC*CC - CC;
        float a = 0.f;
        #pragma unroll 4
        for (int k = 0; k < CC; k++) a = fmaf(b2v[k], f2w[k*CC+c], a);
        g_c2[c] = a;
    }
}

// ---------------------------------------------------------------------------
// Encoder (fused): hidden = relu(x@w1+b1) -> strided smem;
// G1 = hidden@C1 + c1 ; G2 = hidden@C2 + c2.
// ---------------------------------------------------------------------------
__global__ __launch_bounds__(256) void encoder_kernel(
    const float* __restrict__ x,
    const float* __restrict__ w1, const float* __restrict__ b1v)
{
    extern __shared__ float sh[];          // CC*256 floats, strided
    int tid = threadIdx.x;
    int g = blockIdx.x*256 + tid;
    if (g >= BN) return;

    float xr[DD];
    #pragma unroll
    for (int d = 0; d < DD; d++) xr[d] = x[g*DD + d];
    g_pts[g] = make_float4(xr[0], xr[1], xr[2],
                           xr[0]*xr[0] + xr[1]*xr[1] + xr[2]*xr[2]);

    float acc[CC];

    {
        const float4* bq = (const float4*)b1v;
        #pragma unroll
        for (int c4 = 0; c4 < CC/4; c4++) {
            float4 bv = bq[c4];
            acc[c4*4+0]=bv.x; acc[c4*4+1]=bv.y; acc[c4*4+2]=bv.z; acc[c4*4+3]=bv.w;
        }
        #pragma unroll
        for (int d = 0; d < DD; d++) {
            float xv = xr[d];
            const float4* wv = (const float4*)(w1 + d*CC);
            #pragma unroll
            for (int c4 = 0; c4 < CC/4; c4++) {
                float4 w = wv[c4];
                acc[c4*4+0] = fmaf(xv, w.x, acc[c4*4+0]);
                acc[c4*4+1] = fmaf(xv, w.y, acc[c4*4+1]);
                acc[c4*4+2] = fmaf(xv, w.z, acc[c4*4+2]);
                acc[c4*4+3] = fmaf(xv, w.w, acc[c4*4+3]);
            }
        }
        #pragma unroll
        for (int c = 0; c < CC; c++) sh[c*256 + tid] = fmaxf(acc[c], 0.f);
    }

    {
        const float4* bq = (const float4*)g_c1;
        #pragma unroll
        for (int c4 = 0; c4 < CC/4; c4++) {
            float4 bv = bq[c4];
            acc[c4*4+0]=bv.x; acc[c4*4+1]=bv.y; acc[c4*4+2]=bv.z; acc[c4*4+3]=bv.w;
        }
        #pragma unroll 1
        for (int j = 0; j < CC; j++) {
            float hv = sh[j*256 + tid];
            const float4* wv = (const float4*)(g_C1 + j*CC);
            #pragma unroll
            for (int c4 = 0; c4 < CC/4; c4++) {
                float4 w = wv[c4];
                acc[c4*4+0] = fmaf(hv, w.x, acc[c4*4+0]);
                acc[c4*4+1] = fmaf(hv, w.y, acc[c4*4+1]);
                acc[c4*4+2] = fmaf(hv, w.z, acc[c4*4+2]);
                acc[c4*4+3] = fmaf(hv, w.w, acc[c4*4+3]);
            }
        }
        float4* o = (float4*)g_G1 + g*(CC/4);
        #pragma unroll
        for (int c4 = 0; c4 < CC/4; c4++)
            o[c4] = make_float4(acc[c4*4+0], acc[c4*4+1], acc[c4*4+2], acc[c4*4+3]);
    }

    {
        const float4* bq = (const float4*)g_c2;
        #pragma unroll
        for (int c4 = 0; c4 < CC/4; c4++) {
            float4 bv = bq[c4];
            acc[c4*4+0]=bv.x; acc[c4*4+1]=bv.y; acc[c4*4+2]=bv.z; acc[c4*4+3]=bv.w;
        }
        #pragma unroll 1
        for (int j = 0; j < CC; j++) {
            float hv = sh[j*256 + tid];
            const float4* wv = (const float4*)(g_C2 + j*CC);
            #pragma unroll
            for (int c4 = 0; c4 < CC/4; c4++) {
                float4 w = wv[c4];
                acc[c4*4+0] = fmaf(hv, w.x, acc[c4*4+0]);
                acc[c4*4+1] = fmaf(hv, w.y, acc[c4*4+1]);
                acc[c4*4+2] = fmaf(hv, w.z, acc[c4*4+2]);
                acc[c4*4+3] = fmaf(hv, w.w, acc[c4*4+3]);
            }
        }
        float4* o = (float4*)g_G2 + g*(CC/4);
        #pragma unroll
        for (int c4 = 0; c4 < CC/4; c4++)
            o[c4] = make_float4(acc[c4*4+0], acc[c4*4+1], acc[c4*4+2], acc[c4*4+3]);
    }
}

// ---------------------------------------------------------------------------
// Group compaction: for each appended group entry (chunk-local j0), re-load
// its 8 candidates from the smem SoA chunk, recompute distances with the
// IDENTICAL per-lane fma sequence (bit-identical), clamp >= 0, pack
// (dist_bits<<32 | global_idx), and insert winners into the 32 strided smem
// result slots (8x4 groups, group maxes in regs). u64 order == top_k order.
// Must be called before the chunk is overwritten. Warp-uniform call sites.
// ---------------------------------------------------------------------------
__device__ __noinline__ void compact_groups(
    const float* __restrict__ sX, const float* __restrict__ sY,
    const float* __restrict__ sZ, const float* __restrict__ sW,
    const unsigned* __restrict__ tapp, int cnt, int jb,
    float qw, float mx, float my, float mz,
    unsigned long long* tslot, unsigned long long* gm,
    unsigned long long& worst, float& thr)
{
    #pragma unroll 1
    for (int a = 0; a < cnt; a++) {
        int j0 = (int)tapp[a*256];
        #pragma unroll 1
        for (int u = 0; u < 8; u++) {
            int j = j0 + u;
            float ss = fmaf(sX[j], mx, sW[j] + qw);
            ss = fmaf(sY[j], my, ss);
            ss = fmaf(sZ[j], mz, ss);
            ss = fmaxf(ss, 0.f);
            unsigned long long v =
                ((unsigned long long)__float_as_uint(ss) << 32)
                | (unsigned)(jb + j);
            if (v < worst) {
                int gsel = 0; unsigned long long gv = gm[0];
                #pragma unroll
                for (int i = 1; i < 8; i++) if (gm[i] > gv) { gv = gm[i]; gsel = i; }
                int base = gsel * 4;
                unsigned long long s0 = tslot[(base+0)*256];
                unsigned long long s1 = tslot[(base+1)*256];
                unsigned long long s2 = tslot[(base+2)*256];
                unsigned long long s3 = tslot[(base+3)*256];
                int e = 0; unsigned long long ev = s0;
                if (s1 > ev) { ev = s1; e = 1; }
                if (s2 > ev) { ev = s2; e = 2; }
                if (s3 > ev) { ev = s3; e = 3; }
                tslot[(base+e)*256] = v;
                unsigned long long n0 = (e==0)?v:s0, n1 = (e==1)?v:s1;
                unsigned long long n2 = (e==2)?v:s2, n3 = (e==3)?v:s3;
                unsigned long long m01 = n0 > n1 ? n0 : n1;
                unsigned long long m23 = n2 > n3 ? n2 : n3;
                unsigned long long ngm = m01 > m23 ? m01 : m23;
                #pragma unroll
                for (int i = 0; i < 8; i++) if (i == gsel) gm[i] = ngm;
                unsigned long long w8 = gm[0];
                #pragma unroll
                for (int i = 1; i < 8; i++) if (gm[i] > w8) w8 = gm[i];
                worst = w8;
            }
        }
    }
    thr = (worst == ~0ull) ? inf_f()
                           : __uint_as_float((unsigned)(worst >> 32));
}

// ---------------------------------------------------------------------------
// Exact 32-NN with group-granular appends: the hot loop appends ONE u32
// (chunk-local j0) per 8-candidate group when min(s0..s7) <= thr — all
// per-candidate bookkeeping (idx pack, prefix, per-elem store) amortized 8x.
// Unclamped min can only over-accept (unclamped <= clamped, thr >= 0);
// compaction recomputes exactly, so no winner is ever missed. Chunks are
// flushed before being overwritten. Zero local memory anywhere.
// ---------------------------------------------------------------------------
__global__ __launch_bounds__(256) void knn_kernel() {
    extern __shared__ char smemraw[];
    float* sX = (float*)smemraw;
    float* sY = sX + CHUNK;
    float* sZ = sY + CHUNK;
    float* sW = sZ + CHUNK;
    unsigned long long* slots = (unsigned long long*)(smemraw + CHUNK*16);
    unsigned* app = (unsigned*)(smemraw + CHUNK*16 + KK*256*8);

    int tid = threadIdx.x;
    int b = blockIdx.y;
    const float4* src = g_pts + b*NN;

    int q = blockIdx.x * 256 + tid;
    if (q >= NN) q = NN - 1;              // clamp (ballot safety)

    float4 me = g_pts[b*NN + q];
    float qw = me.w;
    float mx = -2.f*me.x, my = -2.f*me.y, mz = -2.f*me.z;
    const float INF = inf_f();
    unsigned long long qw2, mx2, my2, mz2;
    PK2(qw2, qw, qw); PK2(mx2, mx, mx); PK2(my2, my, my); PK2(mz2, mz, mz);

    unsigned long long* tslot = slots + tid;
    unsigned* tapp = app + tid;
    unsigned abase0, aptr, atrig;
    {
        unsigned long long l64;
        asm("cvta.to.shared.u64 %0, %1;" : "=l"(l64) : "l"((const void*)tapp));
        abase0 = (unsigned)l64;
    }
    aptr = abase0;
    atrig = abase0 + (CAPG - 5) * 1024u;

    #pragma unroll
    for (int i = 0; i < KK; i++) tslot[i*256] = ~0ull;

    unsigned long long gm[8];
    #pragma unroll
    for (int i = 0; i < 8; i++) gm[i] = ~0ull;
    unsigned long long worst = ~0ull;
    float thr = INF;

    #pragma unroll 1
    for (int ch = 0; ch < NN/CHUNK; ch++) {          // 4 chunks
        __syncthreads();                             // prev chunk fully done
        {
            const float4* csrc = src + ch*CHUNK;
            #pragma unroll
            for (int k = 0; k < CHUNK/256; k++) {    // 7 rounds
                int i = tid + k*256;
                float4 c = csrc[i];
                sX[i] = c.x; sY[i] = c.y; sZ[i] = c.z; sW[i] = c.w;
            }
            int i = tid + (CHUNK/256)*256;           // remainder (208)
            if (i < CHUNK) {
                float4 c = csrc[i];
                sX[i] = c.x; sY[i] = c.y; sZ[i] = c.z; sW[i] = c.w;
            }
        }
        __syncthreads();

        int jb = ch*CHUNK;
        #pragma unroll 1
        for (int jo = 0; jo < CHUNK/40; jo++) {      // 50 rounds x 5 groups
            #pragma unroll
            for (int gi = 0; gi < 5; gi++) {
                int j0 = jo*40 + gi*8;
                ulonglong2 xv0 = *(const ulonglong2*)(sX + j0);
                ulonglong2 xv1 = *(const ulonglong2*)(sX + j0 + 4);
                ulonglong2 yv0 = *(const ulonglong2*)(sY + j0);
                ulonglong2 yv1 = *(const ulonglong2*)(sY + j0 + 4);
                ulonglong2 zv0 = *(const ulonglong2*)(sZ + j0);
                ulonglong2 zv1 = *(const ulonglong2*)(sZ + j0 + 4);
                ulonglong2 wv0 = *(const ulonglong2*)(sW + j0);
                ulonglong2 wv1 = *(const ulonglong2*)(sW + j0 + 4);
                unsigned long long xp[4] = {xv0.x, xv0.y, xv1.x, xv1.y};
                unsigned long long yp[4] = {yv0.x, yv0.y, yv1.x, yv1.y};
                unsigned long long zp[4] = {zv0.x, zv0.y, zv1.x, zv1.y};
                unsigned long long wp[4] = {wv0.x, wv0.y, wv1.x, wv1.y};
                float pm[4];
                #pragma unroll
                for (int p = 0; p < 4; p++) {
                    unsigned long long d;
                    ADD2(d, wp[p], qw2);
                    FMA2(d, xp[p], mx2, d);
                    FMA2(d, yp[p], my2, d);
                    FMA2(d, zp[p], mz2, d);
                    float lo, hi;
                    UPK2(lo, hi, d);
                    pm[p] = fminf(lo, hi);
                }
                float gmin = fminf(fminf(pm[0], pm[1]), fminf(pm[2], pm[3]));
                unsigned inc;
                asm volatile(
                    "{\n\t"
                    ".reg .pred p;\n\t"
                    "setp.le.f32 p, %1, %2;\n\t"
                    "@p st.shared.b32 [%3], %4;\n\t"
                    "selp.u32 %0, 1024, 0, p;\n\t"
                    "}"
                    : "=r"(inc)
                    : "f"(gmin), "f"(thr), "r"(aptr), "r"((unsigned)j0)
                    : "memory");
                aptr += inc;
            }
            if (__any_sync(0xffffffffu, aptr >= atrig)) {
                int cnt = (int)((aptr - abase0) >> 10);
                compact_groups(sX, sY, sZ, sW, tapp, cnt, jb,
                               qw, mx, my, mz, tslot, gm, worst, thr);
                aptr = abase0;
            }
        }
        // flush before chunk swap (entries reference this chunk's smem)
        {
            int cnt = (int)((aptr - abase0) >> 10);
            compact_groups(sX, sY, sZ, sW, tapp, cnt, jb,
                           qw, mx, my, mz, tslot, gm, worst, thr);
            aptr = abase0;
        }
    }

    int* o = g_idx + (b*NN + q)*KK;
    #pragma unroll 1
    for (int i = 0; i < KK; i++)
        o[i] = (int)(unsigned)tslot[i*256];
}

// ---------------------------------------------------------------------------
// Fuse (both branches) + classifier.
// ---------------------------------------------------------------------------
__global__ __launch_bounds__(256) void fuse_kernel(
    const float* __restrict__ f1b, const float* __restrict__ f2b,
    const float* __restrict__ cw1, const float* __restrict__ cb1,
    const float* __restrict__ cw2, const float* __restrict__ cb2,
    float* __restrict__ out)
{
    __shared__ float sfused[4][CC];
    __shared__ float shid[4][CC/2];
    __shared__ int   sidx[4][KK];

    int tid = threadIdx.x;
    int p = tid >> 6, c = tid & 63;
    int g = blockIdx.x*4 + p;

    if (c < KK) sidx[p][c] = g_idx[g*KK + c];
    __syncthreads();

    int b = g / NN;
    int rowbase = b*NN;

    float g1i = g_G1[g*CC + c];
    float g2i = g_G2[g*CC + c];
    float bb1 = f1b[c] - g1i;
    float bb2 = f2b[c] - g2i;
    float m1 = 0.f, m2 = 0.f;
    #pragma unroll 8
    for (int k = 0; k < KK; k++) {
        int j = sidx[p][k] + rowbase;
        m1 = fmaxf(m1, g_G1[j*CC + c] + bb1);
        m2 = fmaxf(m2, g_G2[j*CC + c] + bb2);
    }
    sfused[p][c] = m1 + m2;
    __syncthreads();

    if (c < CC/2) {
        float a = cb1[c];
        #pragma unroll
        for (int u = 0; u < CC; u++) a = fmaf(sfused[p][u], cw1[u*(CC/2) + c], a);
        shid[p][c] = fmaxf(a, 0.f);
    }
    __syncthreads();

    if (c < NCLS) {
        float a = cb2[c];
        #pragma unroll
        for (int u = 0; u < CC/2; u++) a = fmaf(shid[p][u], cw2[u*NCLS + c], a);
        out[g*NCLS + c] = a;
    }
}

extern "C" void kernel_launch(void* const* d_in, const int* in_sizes, int n_in,
                              void* d_out, int out_size) {
    const float* x      = (const float*)d_in[0];
    const float* enc_w1 = (const float*)d_in[1];
    const float* enc_b1 = (const float*)d_in[2];
    const float* enc_w2 = (const float*)d_in[3];
    const float* enc_b2 = (const float*)d_in[4];
    const float* f1_w   = (const float*)d_in[5];
    const float* f1_b   = (const float*)d_in[6];
    const float* f2_w   = (const float*)d_in[7];
    const float* f2_b   = (const float*)d_in[8];
    const float* cls_w1 = (const float*)d_in[9];
    const float* cls_b1 = (const float*)d_in[10];
    const float* cls_w2 = (const float*)d_in[11];
    const float* cls_b2 = (const float*)d_in[12];

    precompute_kernel<<<(2*CC*CC + 2*CC + 255)/256, 256>>>(enc_w2, enc_b2,
                                                           f1_w, f2_w);

    const int enc_smem = CC * 256 * (int)sizeof(float);   // 65536
    cudaFuncSetAttribute(encoder_kernel,
                         cudaFuncAttributeMaxDynamicSharedMemorySize, enc_smem);
    encoder_kernel<<<(BN + 255)/256, 256, enc_smem>>>(x, enc_w1, enc_b1);

    // 32000 (chunk) + 65536 (result slots) + 81920 (appends) = 179456
    const int knn_smem = CHUNK*16 + KK*256*8 + CAPG*256*4;
    cudaFuncSetAttribute(knn_kernel, cudaFuncAttributeMaxDynamicSharedMemorySize,
                         knn_smem);
    dim3 kg((NN + 255)/256, BB);
    knn_kernel<<<kg, 256, knn_smem>>>();

    fuse_kernel<<<BN/4, 256>>>(f1_b, f2_b, cls_w1, cls_b1, cls_w2, cls_b2,
                               (float*)d_out);
}